// round 17
// baseline (speedup 1.0000x reference)
#include <cuda_runtime.h>

#define H       128
#define SEQ     1024
#define MBLK    4
#define NCTAS   128
#define NTHR    256
#define COUT    10

#define NG      16          // 4-k groups per thread (64 k's, kh half)
#define RG      7           // register-resident weight groups (7*16 = 112 regs)
#define PFG     2           // groups prefetched during the tail
#define SG      (NG - RG)   // 9 groups in smem (2 prefetched, 7 in-loop)

#define HSTRIDE 136         // h row stride in floats (mod 32 = 8 -> bank spread)
#define HBUF    (MBLK * HSTRIDE)    // 544 floats

// h skew: float offset of h[k] within a row = k + (k>>6)*4
// kh=1 half starts at 68 floats -> +4 banks vs kh=0: the two 16B spans of a
// broadcast load are bank-disjoint -> 1 wavefront.
__device__ __forceinline__ int hoff(int k) { return k + ((k >> 6) << 2); }

// ---- dynamic smem layout (bytes, 16B aligned) ----
#define WS_OFF    0
#define WS_BYTES  (SG * 4 * NTHR * 16)      // 147456: float4 [(sg*4+q)][tid]
#define XS_OFF    (WS_OFF + WS_BYTES)
#define XS_BYTES  (MBLK * SEQ * 4)          // 16384
#define WPS_OFF   (XS_OFF + XS_BYTES)
#define WPS_BYTES (H * COUT * 4)            // 5120
#define HB_OFF    (WPS_OFF + WPS_BYTES)
#define HB_BYTES  (2 * HBUF * 4)            // 4352
#define SMEM_TOTAL (HB_OFF + HB_BYTES + 64) // ~173 KB (55 KB L1D left)

// Fused LSTM cell (validated rel_err ~2.8e-7 across R8-R16). Overflow-safe.
__device__ __forceinline__ float lstm_cell(float zg, float zi, float zf, float zo, float& c) {
    float eg = __expf(-2.0f * fabsf(zg));
    float ei = __expf(-zi);
    float ef = __expf(-zf);
    float eo = __expf(-zo);
    float gi = __fdividef(copysignf(1.0f - eg, zg), (1.0f + eg) * (1.0f + ei));
    float cf = __fdividef(c, 1.0f + ef);
    float cn = gi + cf;
    float ec = __expf(-2.0f * fabsf(cn));
    float h  = __fdividef(copysignf(1.0f - ec, cn), (1.0f + ec) * (1.0f + eo));
    c = cn;
    return h;
}

__global__ void __launch_bounds__(NTHR, 1)
lstm_persistent_kernel(const float* __restrict__ x,
                       const float* __restrict__ Wgx, const float* __restrict__ Wgh, const float* __restrict__ bg,
                       const float* __restrict__ Wix, const float* __restrict__ Wih, const float* __restrict__ bi,
                       const float* __restrict__ Wfx, const float* __restrict__ Wfh, const float* __restrict__ bf,
                       const float* __restrict__ Wox, const float* __restrict__ Woh, const float* __restrict__ bo,
                       const float* __restrict__ Wph, const float* __restrict__ bp,
                       float* __restrict__ out)
{
    extern __shared__ char smem[];
    float4*     ws = (float4*)(smem + WS_OFF);
    float*     xsm = (float*)(smem + XS_OFF);
    float*     wps = (float*)(smem + WPS_OFF);
    float*      hb = (float*)(smem + HB_OFF);   // two skewed h buffers

    const int tid = threadIdx.x;
    const int kh  = tid & 1;        // k-half: [kh*64, kh*64+64); partner = adjacent lane
    const int n   = tid >> 1;       // gate column (owns cols n of all 4 gates)
    const int m0  = blockIdx.x * MBLK;
    const int mr  = kh * 2;         // this thread's gate-phase rows: mr, mr+1
    const int om  = 2 - mr;         // partner's rows

    // ---- smem weights: groups RG..NG-1 of slice (kh, n) ----
    // ws[(sg*4+q)*NTHR + tid] = {Wgh, Wih, Wfh, Woh} at k = k0+q
#pragma unroll
    for (int sg = 0; sg < SG; sg++) {
        int k0 = kh * 64 + (RG + sg) * 4;
#pragma unroll
        for (int q = 0; q < 4; q++) {
            float4 v;
            v.x = Wgh[(k0+q)*H+n];
            v.y = Wih[(k0+q)*H+n];
            v.z = Wfh[(k0+q)*H+n];
            v.w = Woh[(k0+q)*H+n];
            ws[(sg*4+q)*NTHR + tid] = v;
        }
    }

    // ---- register weights: groups 0..RG-1 (16 floats each = 112 regs) ----
    float wreg[RG][16];
#pragma unroll
    for (int g = 0; g < RG; g++) {
        int k0 = kh * 64 + g * 4;
#pragma unroll
        for (int q = 0; q < 4; q++) {
            wreg[g][q*4+0] = Wgh[(k0+q)*H+n];
            wreg[g][q*4+1] = Wih[(k0+q)*H+n];
            wreg[g][q*4+2] = Wfh[(k0+q)*H+n];
            wreg[g][q*4+3] = Woh[(k0+q)*H+n];
        }
    }

    // ---- gate-phase params: thread owns cells (mr, n), (mr+1, n) ----
    const float wxg = Wgx[n], wxi = Wix[n], wxf = Wfx[n], wxo = Wox[n];
    float bG[2], bI[2], bF[2], bO[2];
#pragma unroll
    for (int j = 0; j < 2; j++) {
        bG[j] = bg[(m0+mr+j)*H+n];
        bI[j] = bi[(m0+mr+j)*H+n];
        bF[j] = bf[(m0+mr+j)*H+n];
        bO[j] = bo[(m0+mr+j)*H+n];
    }

    // ---- preload x, Wph, zero both h buffers ----
    for (int i = tid; i < MBLK * SEQ; i += NTHR) {
        int mm = i >> 10, tt = i & (SEQ - 1);
        xsm[i] = x[(m0+mm)*SEQ + tt];
    }
    for (int i = tid; i < H * COUT; i += NTHR) wps[i] = Wph[i];
    for (int i = tid; i < 2 * HBUF; i += NTHR) hb[i] = 0.0f;
    float c0 = 0.0f, c1 = 0.0f;
    __syncthreads();

    // per-thread constant offsets
    const int hload0 = kh * 68;                         // skewed base of this kh half
    const int hst0 = (mr + 0) * HSTRIDE + hoff(n);      // own h store offsets
    const int hst1 = (mr + 1) * HSTRIDE + hoff(n);
    const float* x0 = xsm + (mr + 0) * SEQ;
    const float* x1 = xsm + (mr + 1) * SEQ;

    // ---- initial prefetch of smem groups RG..RG+PFG-1 ----
    float4 pf[PFG * 4];
#pragma unroll
    for (int i = 0; i < PFG * 4; i++) pf[i] = ws[i * NTHR + tid];

    // ---- time loop: ONE barrier per step ----
    for (int t = 0; t < SEQ; t++) {
        const float* hr = hb + ((t & 1) ? HBUF : 0);
        float*       hw = hb + ((t & 1) ? 0 : HBUF);

        // accE: even-k partial (k0,k2 of each group); accO: odd-k (k1,k3)
        // -> identical accumulation split/order as the R8 f32x2 lanes.
        float accE[4][4], accO[4][4];
#pragma unroll
        for (int gg = 0; gg < 4; gg++)
#pragma unroll
            for (int m = 0; m < 4; m++) { accE[gg][m] = 0.0f; accO[gg][m] = 0.0f; }

#pragma unroll
        for (int g = 0; g < NG; g++) {
            float4 q0, q1, q2, q3;   // weights {g,i,f,o} at k0..k3
            if (g < RG) {
                q0 = make_float4(wreg[g][0],  wreg[g][1],  wreg[g][2],  wreg[g][3]);
                q1 = make_float4(wreg[g][4],  wreg[g][5],  wreg[g][6],  wreg[g][7]);
                q2 = make_float4(wreg[g][8],  wreg[g][9],  wreg[g][10], wreg[g][11]);
                q3 = make_float4(wreg[g][12], wreg[g][13], wreg[g][14], wreg[g][15]);
            } else if (g < RG + PFG) {
                int b = (g - RG) * 4;
                q0 = pf[b+0]; q1 = pf[b+1]; q2 = pf[b+2]; q3 = pf[b+3];
            } else {
                int sg = g - RG;
                q0 = ws[(sg*4+0)*NTHR + tid];
                q1 = ws[(sg*4+1)*NTHR + tid];
                q2 = ws[(sg*4+2)*NTHR + tid];
                q3 = ws[(sg*4+3)*NTHR + tid];
            }
            const int hbase = hload0 + (g << 2);
#pragma unroll
            for (int m = 0; m < 4; m++) {
                // broadcast 16B: {h[k0..k3]} of row m; 2 kh spans bank-disjoint -> 1 wf
                float4 hu = *(const float4*)(hr + m * HSTRIDE + hbase);
                accE[0][m] = fmaf(hu.x, q0.x, accE[0][m]);
                accE[1][m] = fmaf(hu.x, q0.y, accE[1][m]);
                accE[2][m] = fmaf(hu.x, q0.z, accE[2][m]);
                accE[3][m] = fmaf(hu.x, q0.w, accE[3][m]);
                accO[0][m] = fmaf(hu.y, q1.x, accO[0][m]);
                accO[1][m] = fmaf(hu.y, q1.y, accO[1][m]);
                accO[2][m] = fmaf(hu.y, q1.z, accO[2][m]);
                accO[3][m] = fmaf(hu.y, q1.w, accO[3][m]);
                accE[0][m] = fmaf(hu.z, q2.x, accE[0][m]);
                accE[1][m] = fmaf(hu.z, q2.y, accE[1][m]);
                accE[2][m] = fmaf(hu.z, q2.z, accE[2][m]);
                accE[3][m] = fmaf(hu.z, q2.w, accE[3][m]);
                accO[0][m] = fmaf(hu.w, q3.x, accO[0][m]);
                accO[1][m] = fmaf(hu.w, q3.y, accO[1][m]);
                accO[2][m] = fmaf(hu.w, q3.z, accO[2][m]);
                accO[3][m] = fmaf(hu.w, q3.w, accO[3][m]);
            }
        }

        // collapse even/odd partials -> p[gate][m]
        float p[4][4];
#pragma unroll
        for (int gg = 0; gg < 4; gg++)
#pragma unroll
            for (int m = 0; m < 4; m++)
                p[gg][m] = accE[gg][m] + accO[gg][m];

        // exchange kh-partials with adjacent lane: send partner's rows, get mine
        float rec[4][2];
#pragma unroll
        for (int gg = 0; gg < 4; gg++)
#pragma unroll
            for (int j = 0; j < 2; j++)
                rec[gg][j] = __shfl_xor_sync(0xFFFFFFFFu, p[gg][om + j], 1);

        // gates for the 2 owned cells
        {
            float xv = x0[t];
            float zg = p[0][mr]   + rec[0][0] + fmaf(xv, wxg, bG[0]);
            float zi = p[1][mr]   + rec[1][0] + fmaf(xv, wxi, bI[0]);
            float zf = p[2][mr]   + rec[2][0] + fmaf(xv, wxf, bF[0]);
            float zo = p[3][mr]   + rec[3][0] + fmaf(xv, wxo, bO[0]);
            hw[hst0] = lstm_cell(zg, zi, zf, zo, c0);
        }
        {
            float xv = x1[t];
            float zg = p[0][mr+1] + rec[0][1] + fmaf(xv, wxg, bG[1]);
            float zi = p[1][mr+1] + rec[1][1] + fmaf(xv, wxi, bI[1]);
            float zf = p[2][mr+1] + rec[2][1] + fmaf(xv, wxf, bF[1]);
            float zo = p[3][mr+1] + rec[3][1] + fmaf(xv, wxo, bO[1]);
            hw[hst1] = lstm_cell(zg, zi, zf, zo, c1);
        }

        // prefetch next step's first PFG smem groups during the tail
#pragma unroll
        for (int i = 0; i < PFG * 4; i++) pf[i] = ws[i * NTHR + tid];

        __syncthreads();   // new h visible; double-buffer makes one barrier sufficient
    }

    // ---- final projection: h ends in buffer 0 after SEQ (even) steps ----
    const float* hf = hb;
    if (tid < MBLK * COUT) {
        int m = tid / COUT, cc = tid - m * COUT;
        float ssum = bp[(m0+m)*COUT + cc];
#pragma unroll 16
        for (int k = 0; k < H; k++)
            ssum = fmaf(hf[m * HSTRIDE + hoff(k)], wps[k*COUT + cc], ssum);
        out[(m0+m)*COUT + cc] = ssum;
    }
}

extern "C" void kernel_launch(void* const* d_in, const int* in_sizes, int n_in,
                              void* d_out, int out_size) {
    const float* x   = (const float*)d_in[0];
    const float* Wgx = (const float*)d_in[1];
    const float* Wgh = (const float*)d_in[2];
    const float* bg  = (const float*)d_in[3];
    const float* Wix = (const float*)d_in[4];
    const float* Wih = (const float*)d_in[5];
    const float* bi  = (const float*)d_in[6];
    const float* Wfx = (const float*)d_in[7];
    const float* Wfh = (const float*)d_in[8];
    const float* bf  = (const float*)d_in[9];
    const float* Wox = (const float*)d_in[10];
    const float* Woh = (const float*)d_in[11];
    const float* bo  = (const float*)d_in[12];
    const float* Wph = (const float*)d_in[13];
    const float* bp  = (const float*)d_in[14];
    float* out = (float*)d_out;

    cudaFuncSetAttribute(lstm_persistent_kernel,
                         cudaFuncAttributeMaxDynamicSharedMemorySize, SMEM_TOTAL);

    lstm_persistent_kernel<<<NCTAS, NTHR, SMEM_TOTAL>>>(
        x, Wgx, Wgh, bg, Wix, Wih, bi, Wfx, Wfh, bf, Wox, Woh, bo, Wph, bp, out);
}